// round 13
// baseline (speedup 1.0000x reference)
#include <cuda_runtime.h>
#include <cuda_bf16.h>
#include <cstdint>
#include <math.h>

#define Nn 64
#define Ff 256
#define U 4096            // Nn*Nn
#define ROWS 128          // k-chunk rows per gemv block
#define GEMV_TPB 128      // threads per block
#define JBLK 8            // U / (GEMV_TPB*4)
#define KBLK (U / ROWS)   // 32
#define NW (ROWS / 32)    // warps (=4)
#define DEPTH 16          // cp.async pipeline stages
#define NBLK1 (JBLK * KBLK * 3)   // 768 layer-1 blocks
#define NBLK  (2 * NBLK1)         // 1536 total

// scratch (allocation-free rule: __device__ globals; zero-initialized at load)
__device__ float    g_d     [U];        // shared pairwise distances
__device__ float    g_v1    [3 * U];    // layer-1 accumulator
__device__ unsigned g_dready[KBLK];     // ==3 when dist chunk kb ready
__device__ unsigned g_z;                // ==96 when v1/out zeroed
__device__ unsigned g_cnt1  [3 * JBLK]; // layer-1 completion (per b,jb)
__device__ unsigned g_cnt2  [3 * JBLK]; // layer-2 epilogue counters
__device__ unsigned g_done;             // end-of-kernel reset trigger

// ---------------- cp.async helpers ----------------
__device__ __forceinline__ void cp_async16(void* s, const void* g)
{
    unsigned int sa = (unsigned int)__cvta_generic_to_shared(s);
    asm volatile("cp.async.cg.shared.global [%0], [%1], 16;" :: "r"(sa), "l"(g));
}
__device__ __forceinline__ void cp_commit()
{
    asm volatile("cp.async.commit_group;" ::: "memory");
}
template <int N> __device__ __forceinline__ void cp_wait()
{
    asm volatile("cp.async.wait_group %0;" :: "n"(N) : "memory");
}
__device__ __forceinline__ void spin_until(unsigned* c, unsigned target)
{
    while (atomicAdd(c, 0u) < target) __nanosleep(64);
}

// ---------------------------------------------------------------------------
// Single launch, 1536 blocks — R11's proven decoupled structure:
//   bids [0, NBLK1):       layer-1 blocks (b, jb, kb)
//     jb==0: also compute b-th third of dist chunk kb into g_d (phase A)
//     jb==1: also zero v1/out chunk kb for branch b
//     then: wait dist chunk + zeroing -> x = mask(adj_b, g_d) -> split-K GEMV
//           into g_v1 -> publish g_cnt1[b][jb]
//   bids [NBLK1, NBLK):    layer-2 blocks: wait g_cnt1[b][kb/4]==32 ->
//           x = relu(v1 chunk) -> split-K GEMV into out -> last per (b,jb)
//           applies final ReLU.
// All layer-1 blocks are wave-1 resident (768 < ~888 slots) -> no deadlock.
// Last of 1536 blocks resets all counters for the next graph replay.
// ---------------------------------------------------------------------------
__global__ void __launch_bounds__(GEMV_TPB)
fused_mlp_kernel(const float* __restrict__ adj0, const float* __restrict__ adj1,
                 const float* __restrict__ adj2, const float* __restrict__ nv,
                 const float* __restrict__ w0_1, const float* __restrict__ w1_1,
                 const float* __restrict__ w2_1,
                 const float* __restrict__ w0_2, const float* __restrict__ w1_2,
                 const float* __restrict__ w2_2,
                 float* __restrict__ out)
{
    __shared__ float4 stage[DEPTH][GEMV_TPB];   // 32 KB
    __shared__ float  sv[ROWS];
    __shared__ int    sidx[ROWS];
    __shared__ int    warp_off[NW + 1];
    __shared__ int    s_last;

    const int tid  = threadIdx.x;
    const int lane = tid & 31;
    const int w    = tid >> 5;

    const int bid    = blockIdx.x;
    const int layer2 = (bid >= NBLK1) ? 1 : 0;
    const int l      = layer2 ? (bid - NBLK1) : bid;
    const int jb     = l % JBLK;
    const int kb     = (l / JBLK) % KBLK;
    const int b      = l / (JBLK * KBLK);

    const int i0 = kb * ROWS;
    const int j0 = jb * (GEMV_TPB * 4) + tid * 4;

    // ====== phase A (layer-1 helpers): dist chunks + zeroing ================
    if (!layer2 && jb == 0) {
        // compute pairs [i0 + b*ROWS/3, i0 + (b+1)*ROWS/3)
        const int seg_lo = (b * ROWS) / 3;
        const int seg_hi = ((b + 1) * ROWS) / 3;
        for (int p = seg_lo + w; p < seg_hi; p += NW) {
            int pair = i0 + p;
            int i = pair >> 6;
            int j = pair & 63;
            const float4* ri = (const float4*)(nv + i * Ff);
            const float4* rj = (const float4*)(nv + j * Ff);
            float4 a0 = __ldg(ri + lane);
            float4 a1 = __ldg(ri + lane + 32);
            float4 b0 = __ldg(rj + lane);
            float4 b1 = __ldg(rj + lane + 32);
            float s = 0.0f, d;
            d = a0.x - b0.x; s = fmaf(d, d, s);
            d = a0.y - b0.y; s = fmaf(d, d, s);
            d = a0.z - b0.z; s = fmaf(d, d, s);
            d = a0.w - b0.w; s = fmaf(d, d, s);
            d = a1.x - b1.x; s = fmaf(d, d, s);
            d = a1.y - b1.y; s = fmaf(d, d, s);
            d = a1.z - b1.z; s = fmaf(d, d, s);
            d = a1.w - b1.w; s = fmaf(d, d, s);
            #pragma unroll
            for (int off = 16; off > 0; off >>= 1)
                s += __shfl_down_sync(0xffffffffu, s, off);
            if (lane == 0) g_d[pair] = sqrtf(s);
        }
        __threadfence();
        __syncthreads();
        if (tid == 0) atomicAdd(&g_dready[kb], 1u);
    }
    if (!layer2 && jb == 1) {
        // zero v1/out chunk kb for branch b
        g_v1[b * U + i0 + tid] = 0.0f;
        out [b * U + i0 + tid] = 0.0f;
        __threadfence();
        __syncthreads();
        if (tid == 0) atomicAdd(&g_z, 1u);
    }

    // ====== acquire inputs ==================================================
    const float* W;
    float*       y;
    float        v;
    if (!layer2) {
        if (tid == 0) {
            spin_until(&g_dready[kb], 3u);
            spin_until(&g_z, 96u);
        }
        __syncthreads();
        __threadfence();
        W = (b == 0) ? w0_1 : (b == 1) ? w1_1 : w2_1;
        y = g_v1;
        const float* adj = (b == 0) ? adj0 : (b == 1) ? adj1 : adj2;
        float dv = g_d[i0 + tid];
        v = (__ldg(adj + i0 + tid) == 1.0f) ? dv : 0.0f;
    } else {
        if (tid == 0) spin_until(&g_cnt1[b * JBLK + (kb >> 2)], (unsigned)KBLK);
        __syncthreads();
        __threadfence();
        W = (b == 0) ? w0_2 : (b == 1) ? w1_2 : w2_2;
        y = out;
        v = fmaxf(g_v1[b * U + i0 + tid], 0.0f);
    }

    // ====== deterministic compaction of nonzero x entries ===================
    bool nz = (v != 0.0f);
    unsigned m = __ballot_sync(0xffffffffu, nz);
    if (lane == 0) warp_off[w] = __popc(m);
    __syncthreads();
    if (tid == 0) {
        int s = 0;
        #pragma unroll
        for (int ww = 0; ww < NW; ww++) {
            int c = warp_off[ww];
            warp_off[ww] = s;
            s += c;
        }
        warp_off[NW] = s;
    }
    __syncthreads();
    if (nz) {
        int p = warp_off[w] + __popc(m & ((1u << lane) - 1u));
        sv[p]   = v;
        sidx[p] = i0 + tid;
    }
    __syncthreads();
    const int cnt = warp_off[NW];

    // ====== streaming split-K GEMV (cp.async pipeline) ======================
    const float* Wb = W + (size_t)j0;
    float4 acc = make_float4(0.f, 0.f, 0.f, 0.f);

    #pragma unroll
    for (int s = 0; s < DEPTH; s++) {
        if (s < cnt)
            cp_async16(&stage[s][tid], Wb + (size_t)sidx[s] * U);
        cp_commit();
    }
    for (int k = 0; k < cnt; k++) {
        cp_wait<DEPTH - 1>();
        float4 a = stage[k & (DEPTH - 1)][tid];
        float  c = sv[k];
        int n = k + DEPTH;
        if (n < cnt)
            cp_async16(&stage[n & (DEPTH - 1)][tid], Wb + (size_t)sidx[n] * U);
        cp_commit();
        acc.x = fmaf(c, a.x, acc.x);
        acc.y = fmaf(c, a.y, acc.y);
        acc.z = fmaf(c, a.z, acc.z);
        acc.w = fmaf(c, a.w, acc.w);
    }
    cp_wait<0>();

    float* yp = y + b * U + j0;
    atomicAdd(yp + 0, acc.x);
    atomicAdd(yp + 1, acc.y);
    atomicAdd(yp + 2, acc.z);
    atomicAdd(yp + 3, acc.w);

    // ====== publish / epilogue ==============================================
    if (!layer2) {
        __threadfence();
        __syncthreads();
        if (tid == 0) atomicAdd(&g_cnt1[b * JBLK + jb], 1u);
    } else {
        __threadfence();
        __syncthreads();
        if (tid == 0) {
            unsigned old = atomicAdd(&g_cnt2[b * JBLK + jb], 1u);
            s_last = (old == KBLK - 1) ? 1 : 0;
        }
        __syncthreads();
        if (s_last) {
            float r0 = __ldcg(yp + 0);
            float r1 = __ldcg(yp + 1);
            float r2 = __ldcg(yp + 2);
            float r3 = __ldcg(yp + 3);
            yp[0] = fmaxf(r0, 0.0f);
            yp[1] = fmaxf(r1, 0.0f);
            yp[2] = fmaxf(r2, 0.0f);
            yp[3] = fmaxf(r3, 0.0f);
        }
    }

    // last of all 1536 blocks resets counters for the next graph replay
    if (tid == 0) {
        __threadfence();
        unsigned old = atomicAdd(&g_done, 1u);
        if (old == NBLK - 1) {
            for (int i = 0; i < KBLK; i++)     g_dready[i] = 0u;
            for (int i = 0; i < 3 * JBLK; i++) { g_cnt1[i] = 0u; g_cnt2[i] = 0u; }
            g_z = 0u;
            __threadfence();
            g_done = 0u;
            __threadfence();
        }
    }
}

extern "C" void kernel_launch(void* const* d_in, const int* in_sizes, int n_in,
                              void* d_out, int out_size)
{
    const float* adj0 = (const float*)d_in[0];
    const float* adj1 = (const float*)d_in[1];
    const float* adj2 = (const float*)d_in[2];
    const float* nv   = (const float*)d_in[3];
    const float* w0_1 = (const float*)d_in[4];
    const float* w0_2 = (const float*)d_in[5];
    const float* w1_1 = (const float*)d_in[6];
    const float* w1_2 = (const float*)d_in[7];
    const float* w2_1 = (const float*)d_in[8];
    const float* w2_2 = (const float*)d_in[9];
    float* out = (float*)d_out;

    fused_mlp_kernel<<<NBLK, GEMV_TPB>>>(adj0, adj1, adj2, nv,
                                         w0_1, w1_1, w2_1,
                                         w0_2, w1_2, w2_2, out);
}

// round 15
// speedup vs baseline: 1.0143x; 1.0143x over previous
#include <cuda_runtime.h>
#include <cuda_bf16.h>
#include <cstdint>
#include <math.h>

#define Nn 64
#define Ff 256
#define U 4096            // Nn*Nn
#define ROWS 128          // k-chunk rows per gemv block
#define GEMV_TPB 128      // threads per block
#define JBLK 8            // U / (GEMV_TPB*4)
#define KBLK (U / ROWS)   // 32
#define NW (ROWS / 32)    // warps (=4)
#define DEPTH 16          // cp.async pipeline stages
#define NBLK1 (JBLK * KBLK * 3)   // 768 layer-1 blocks
#define NBLK  (2 * NBLK1)         // 1536 total

// scratch (allocation-free rule: __device__ globals; zero-initialized at load)
__device__ float    g_v1   [3 * U];     // layer-1 accumulator (kept zero across replays)
__device__ unsigned g_cnt1 [3 * JBLK];  // layer-1 completion (per b,jb)
__device__ unsigned g_cnt2 [3 * JBLK];  // layer-2 epilogue counters
__device__ unsigned g_vread[3 * KBLK];  // v1-chunk consumer counters (re-zero trigger)
__device__ unsigned g_zout;             // ==24 when out fully zeroed
__device__ unsigned g_done;             // end-of-kernel reset trigger

// ---------------- cp.async helpers ----------------
__device__ __forceinline__ void cp_async16(void* s, const void* g)
{
    unsigned int sa = (unsigned int)__cvta_generic_to_shared(s);
    asm volatile("cp.async.cg.shared.global [%0], [%1], 16;" :: "r"(sa), "l"(g));
}
__device__ __forceinline__ void cp_commit()
{
    asm volatile("cp.async.commit_group;" ::: "memory");
}
template <int N> __device__ __forceinline__ void cp_wait()
{
    asm volatile("cp.async.wait_group %0;" :: "n"(N) : "memory");
}
__device__ __forceinline__ void spin_until(unsigned* c, unsigned target)
{
    while (atomicAdd(c, 0u) < target) __nanosleep(64);
}

// ---------------------------------------------------------------------------
// Single launch, 1536 blocks (R11's proven decoupled split-K structure).
//   L1 block (b, jb, kb):  compaction directly from adj (no dependency!),
//     cp.async weight prefetch starts immediately; the block computes the
//     distances for its compacted rows itself while the prefetch is in
//     flight (nv is L2-resident). kb==0 blocks also zero their out slice.
//   L2 block (b, jb, kb):  waits g_cnt1[b][kb/4]==32 and g_zout==24, then
//     relu(v1 chunk) -> GEMV into out; last per (b,jb) applies final ReLU;
//     8th reader of each v1 chunk re-zeroes it for the next graph replay.
// All L1 blocks are wave-1 resident (768 < ~888 slots) -> spinners can't
// starve producers. Last of 1536 blocks resets counters for next replay.
// ---------------------------------------------------------------------------
__global__ void __launch_bounds__(GEMV_TPB)
fused_mlp_kernel(const float* __restrict__ adj0, const float* __restrict__ adj1,
                 const float* __restrict__ adj2, const float* __restrict__ nv,
                 const float* __restrict__ w0_1, const float* __restrict__ w1_1,
                 const float* __restrict__ w2_1,
                 const float* __restrict__ w0_2, const float* __restrict__ w1_2,
                 const float* __restrict__ w2_2,
                 float* __restrict__ out)
{
    __shared__ float4 stage[DEPTH][GEMV_TPB];   // 32 KB
    __shared__ float  sv[ROWS];
    __shared__ int    sidx[ROWS];
    __shared__ int    warp_off[NW + 1];
    __shared__ int    s_last;
    __shared__ int    s_rezero;

    const int tid  = threadIdx.x;
    const int lane = tid & 31;
    const int w    = tid >> 5;

    const int bid    = blockIdx.x;
    const int layer2 = (bid >= NBLK1) ? 1 : 0;
    const int l      = layer2 ? (bid - NBLK1) : bid;
    const int jb     = l % JBLK;
    const int kb     = (l / JBLK) % KBLK;
    const int b      = l / (JBLK * KBLK);

    const int i0 = kb * ROWS;
    const int j0 = jb * (GEMV_TPB * 4) + tid * 4;

    const float* W;
    float*       y;
    bool         nz;
    float        v = 0.0f;

    if (!layer2) {
        // ---- zero out slice (kb==0 blocks), no waiting for anyone ----
        if (kb == 0) {
            ((float4*)(out + b * U + jb * (GEMV_TPB * 4)))[tid] =
                make_float4(0.f, 0.f, 0.f, 0.f);
            __threadfence();
            __syncthreads();
            if (tid == 0) atomicAdd(&g_zout, 1u);
        }
        W = (b == 0) ? w0_1 : (b == 1) ? w1_1 : w2_1;
        y = g_v1;
        const float* adj = (b == 0) ? adj0 : (b == 1) ? adj1 : adj2;
        // nonzero pattern from adj alone: adj==1 and i!=j (diagonal dist==0)
        int pair = i0 + tid;
        int pi = pair >> 6, pj = pair & 63;
        nz = (__ldg(adj + pair) == 1.0f) && (pi != pj);
    } else {
        // ---- wait for producers of v1 chunk kb (and out zeroing) ----
        if (tid == 0) {
            spin_until(&g_cnt1[b * JBLK + (kb >> 2)], (unsigned)KBLK);
            spin_until(&g_zout, 24u);
        }
        __syncthreads();
        __threadfence();
        W = (b == 0) ? w0_2 : (b == 1) ? w1_2 : w2_2;
        y = out;
        v = fmaxf(g_v1[b * U + i0 + tid], 0.0f);
        nz = (v != 0.0f);
    }

    // ====== deterministic compaction ========================================
    unsigned m = __ballot_sync(0xffffffffu, nz);
    if (lane == 0) warp_off[w] = __popc(m);
    __syncthreads();
    if (tid == 0) {
        int s = 0;
        #pragma unroll
        for (int ww = 0; ww < NW; ww++) {
            int c = warp_off[ww];
            warp_off[ww] = s;
            s += c;
        }
        warp_off[NW] = s;
    }
    __syncthreads();
    if (nz) {
        int p = warp_off[w] + __popc(m & ((1u << lane) - 1u));
        sidx[p] = i0 + tid;
        if (layer2) sv[p] = v;
    }
    __syncthreads();
    const int cnt = warp_off[NW];

    // ---- L2: 8th reader of this v1 chunk re-zeroes it for the next replay --
    if (layer2) {
        if (tid == 0)
            s_rezero = (atomicAdd(&g_vread[b * KBLK + kb], 1u) == 7u) ? 1 : 0;
        __syncthreads();
        if (s_rezero) g_v1[b * U + i0 + tid] = 0.0f;
    }

    // ====== start weight prefetch immediately (DRAM streaming) ==============
    const float* Wb = W + (size_t)j0;
    #pragma unroll
    for (int s = 0; s < DEPTH; s++) {
        if (s < cnt)
            cp_async16(&stage[s][tid], Wb + (size_t)sidx[s] * U);
        cp_commit();
    }

    // ====== L1: compute needed distances UNDER the prefetch shadow ==========
    if (!layer2) {
        for (int p = w; p < cnt; p += NW) {
            int pair = sidx[p];
            int i = pair >> 6;
            int j = pair & 63;
            const float4* ri = (const float4*)(nv + i * Ff);
            const float4* rj = (const float4*)(nv + j * Ff);
            float4 a0 = __ldg(ri + lane);
            float4 a1 = __ldg(ri + lane + 32);
            float4 b0 = __ldg(rj + lane);
            float4 b1 = __ldg(rj + lane + 32);
            float s = 0.0f, d;
            d = a0.x - b0.x; s = fmaf(d, d, s);
            d = a0.y - b0.y; s = fmaf(d, d, s);
            d = a0.z - b0.z; s = fmaf(d, d, s);
            d = a0.w - b0.w; s = fmaf(d, d, s);
            d = a1.x - b1.x; s = fmaf(d, d, s);
            d = a1.y - b1.y; s = fmaf(d, d, s);
            d = a1.z - b1.z; s = fmaf(d, d, s);
            d = a1.w - b1.w; s = fmaf(d, d, s);
            #pragma unroll
            for (int off = 16; off > 0; off >>= 1)
                s += __shfl_down_sync(0xffffffffu, s, off);
            if (lane == 0) sv[p] = sqrtf(s);
        }
        __syncthreads();   // sv ready for all threads
    }

    // ====== streaming consume loop ==========================================
    float4 acc = make_float4(0.f, 0.f, 0.f, 0.f);
    for (int k = 0; k < cnt; k++) {
        cp_wait<DEPTH - 1>();
        float4 a = stage[k & (DEPTH - 1)][tid];
        float  c = sv[k];
        int n = k + DEPTH;
        if (n < cnt)
            cp_async16(&stage[n & (DEPTH - 1)][tid], Wb + (size_t)sidx[n] * U);
        cp_commit();
        acc.x = fmaf(c, a.x, acc.x);
        acc.y = fmaf(c, a.y, acc.y);
        acc.z = fmaf(c, a.z, acc.z);
        acc.w = fmaf(c, a.w, acc.w);
    }
    cp_wait<0>();

    float* yp = y + b * U + j0;
    atomicAdd(yp + 0, acc.x);
    atomicAdd(yp + 1, acc.y);
    atomicAdd(yp + 2, acc.z);
    atomicAdd(yp + 3, acc.w);

    // ====== publish / epilogue ==============================================
    if (!layer2) {
        __threadfence();
        __syncthreads();
        if (tid == 0) atomicAdd(&g_cnt1[b * JBLK + jb], 1u);
    } else {
        __threadfence();
        __syncthreads();
        if (tid == 0) {
            unsigned old = atomicAdd(&g_cnt2[b * JBLK + jb], 1u);
            s_last = (old == KBLK - 1) ? 1 : 0;
        }
        __syncthreads();
        if (s_last) {
            float r0 = __ldcg(yp + 0);
            float r1 = __ldcg(yp + 1);
            float r2 = __ldcg(yp + 2);
            float r3 = __ldcg(yp + 3);
            yp[0] = fmaxf(r0, 0.0f);
            yp[1] = fmaxf(r1, 0.0f);
            yp[2] = fmaxf(r2, 0.0f);
            yp[3] = fmaxf(r3, 0.0f);
        }
    }

    // last of all 1536 blocks resets counters for the next graph replay
    if (tid == 0) {
        __threadfence();
        unsigned old = atomicAdd(&g_done, 1u);
        if (old == NBLK - 1) {
            for (int i = 0; i < 3 * JBLK; i++) { g_cnt1[i] = 0u; g_cnt2[i] = 0u; }
            for (int i = 0; i < 3 * KBLK; i++) g_vread[i] = 0u;
            g_zout = 0u;
            __threadfence();
            g_done = 0u;
            __threadfence();
        }
    }
}

extern "C" void kernel_launch(void* const* d_in, const int* in_sizes, int n_in,
                              void* d_out, int out_size)
{
    const float* adj0 = (const float*)d_in[0];
    const float* adj1 = (const float*)d_in[1];
    const float* adj2 = (const float*)d_in[2];
    const float* nv   = (const float*)d_in[3];
    const float* w0_1 = (const float*)d_in[4];
    const float* w0_2 = (const float*)d_in[5];
    const float* w1_1 = (const float*)d_in[6];
    const float* w1_2 = (const float*)d_in[7];
    const float* w2_1 = (const float*)d_in[8];
    const float* w2_2 = (const float*)d_in[9];
    float* out = (float*)d_out;

    fused_mlp_kernel<<<NBLK, GEMV_TPB>>>(adj0, adj1, adj2, nv,
                                         w0_1, w1_1, w2_1,
                                         w0_2, w1_2, w2_2, out);
}

// round 16
// speedup vs baseline: 1.1471x; 1.1309x over previous
#include <cuda_runtime.h>
#include <cuda_bf16.h>
#include <cstdint>
#include <math.h>

#define Nn 64
#define Ff 256
#define U 4096            // Nn*Nn
#define ROWS 128          // k-chunk rows per gemv block
#define GEMV_TPB 128      // threads per block
#define JBLK 8            // U / (GEMV_TPB*4)
#define KBLK (U / ROWS)   // 32
#define NW (ROWS / 32)    // warps (=4)
#define DEPTH 8           // cp.async stages (halved -> ~18KB smem -> 12 blk/SM, full grid resident)
#define NBLK1 (JBLK * KBLK * 3)   // 768 layer-1 blocks
#define NBLK  (2 * NBLK1)         // 1536 total

// scratch (allocation-free rule: __device__ globals)
__device__ float    g_x   [3 * U];     // masked distance vectors (layer-1 input)
__device__ float    g_v1  [3 * U];     // layer-1 accumulator
__device__ unsigned g_cnt1[3 * JBLK];  // layer-1 completion counters (per b,jblk)
__device__ unsigned g_cnt2[3 * JBLK];  // layer-2 epilogue counters

// ---------------- cp.async helpers ----------------
__device__ __forceinline__ void cp_async16(void* s, const void* g)
{
    unsigned int sa = (unsigned int)__cvta_generic_to_shared(s);
    asm volatile("cp.async.cg.shared.global [%0], [%1], 16;" :: "r"(sa), "l"(g));
}
__device__ __forceinline__ void cp_commit()
{
    asm volatile("cp.async.commit_group;" ::: "memory");
}
template <int N> __device__ __forceinline__ void cp_wait()
{
    asm volatile("cp.async.wait_group %0;" :: "n"(N) : "memory");
}

// ---------------------------------------------------------------------------
// Kernel 1: unique pairwise distances (computed once, shared by 3 branches)
// + zero-init of layer-1 accumulator, d_out, and both counter arrays.
// ---------------------------------------------------------------------------
__global__ void dist_kernel(const float* __restrict__ adj0,
                            const float* __restrict__ adj1,
                            const float* __restrict__ adj2,
                            const float* __restrict__ nv,
                            float* __restrict__ out)
{
    int gtid = blockIdx.x * blockDim.x + threadIdx.x;
    if (gtid < 3 * U) { g_v1[gtid] = 0.0f; out[gtid] = 0.0f; }
    if (gtid < 3 * JBLK) { g_cnt1[gtid] = 0u; g_cnt2[gtid] = 0u; }

    int pair = gtid >> 5;          // warp id = pair id: 0 .. 4095
    int lane = gtid & 31;
    int i = pair >> 6;
    int j = pair & 63;

    const float4* ri = (const float4*)(nv + i * Ff);   // 64 float4s per row
    const float4* rj = (const float4*)(nv + j * Ff);

    float4 a0 = __ldg(ri + lane);
    float4 a1 = __ldg(ri + lane + 32);
    float4 b0 = __ldg(rj + lane);
    float4 b1 = __ldg(rj + lane + 32);

    float s = 0.0f;
    float d;
    d = a0.x - b0.x; s = fmaf(d, d, s);
    d = a0.y - b0.y; s = fmaf(d, d, s);
    d = a0.z - b0.z; s = fmaf(d, d, s);
    d = a0.w - b0.w; s = fmaf(d, d, s);
    d = a1.x - b1.x; s = fmaf(d, d, s);
    d = a1.y - b1.y; s = fmaf(d, d, s);
    d = a1.z - b1.z; s = fmaf(d, d, s);
    d = a1.w - b1.w; s = fmaf(d, d, s);

    #pragma unroll
    for (int off = 16; off > 0; off >>= 1)
        s += __shfl_down_sync(0xffffffffu, s, off);

    if (lane == 0) {
        float dist = sqrtf(s);
        g_x[0 * U + pair] = (__ldg(adj0 + pair) == 1.0f) ? dist : 0.0f;
        g_x[1 * U + pair] = (__ldg(adj1 + pair) == 1.0f) ? dist : 0.0f;
        g_x[2 * U + pair] = (__ldg(adj2 + pair) == 1.0f) ? dist : 0.0f;
    }
}

// ---------------------------------------------------------------------------
// Fused 2-layer sparse-input split-K GEMV (R11 structure, DEPTH=8 for full
// grid residency: 12 blocks/SM x 148 = 1776 slots >= 1536 blocks).
//   bids [0, NBLK1):        layer 1:  v1 = x @ W*_1        (x = masked dists)
//   bids [NBLK1, 2*NBLK1):  layer 2:  out = relu(relu(v1) @ W*_2)
// Layer-2 block (b,kb) spins on g_cnt1[b][kb/4] == KBLK. All blocks resident
// wave-1 -> consumers start the moment their chunk is ready.
// ---------------------------------------------------------------------------
__global__ void __launch_bounds__(GEMV_TPB, 12)
fused_mlp_kernel(const float* __restrict__ w0_1, const float* __restrict__ w1_1,
                 const float* __restrict__ w2_1,
                 const float* __restrict__ w0_2, const float* __restrict__ w1_2,
                 const float* __restrict__ w2_2,
                 float* __restrict__ out)
{
    __shared__ float4 stage[DEPTH][GEMV_TPB];   // 8 * 128 * 16B = 16 KB
    __shared__ float  sv[ROWS];
    __shared__ int    sidx[ROWS];
    __shared__ int    warp_off[NW + 1];
    __shared__ int    s_last;

    const int tid  = threadIdx.x;
    const int lane = tid & 31;
    const int w    = tid >> 5;

    const int bid    = blockIdx.x;
    const int layer2 = (bid >= NBLK1) ? 1 : 0;
    const int l      = layer2 ? (bid - NBLK1) : bid;
    const int jb     = l % JBLK;
    const int kb     = (l / JBLK) % KBLK;
    const int b      = l / (JBLK * KBLK);

    const int i0 = kb * ROWS;
    const int j0 = jb * (GEMV_TPB * 4) + tid * 4;

    const float* W;
    const float* x;
    float*       y;
    if (!layer2) {
        W = (b == 0) ? w0_1 : (b == 1) ? w1_1 : w2_1;
        x = g_x;
        y = g_v1;
    } else {
        W = (b == 0) ? w0_2 : (b == 1) ? w1_2 : w2_2;
        x = g_v1;
        y = out;
        // wait for the 32 layer-1 producers of v1[b, i0 .. i0+ROWS)
        if (tid == 0) {
            unsigned* c = &g_cnt1[b * JBLK + (kb >> 2)];
            while (atomicAdd(c, 0u) < KBLK) __nanosleep(128);
        }
        __syncthreads();   // all threads see counter-protected v1
        __threadfence();
    }

    // deterministic compaction of nonzero x entries in [i0, i0+ROWS)
    float v = x[b * U + i0 + tid];
    if (layer2) v = fmaxf(v, 0.0f);          // relu on layer-2 input
    bool nz = (v != 0.0f);
    unsigned m = __ballot_sync(0xffffffffu, nz);
    if (lane == 0) warp_off[w] = __popc(m);
    __syncthreads();
    if (tid == 0) {
        int s = 0;
        #pragma unroll
        for (int ww = 0; ww < NW; ww++) {
            int c = warp_off[ww];
            warp_off[ww] = s;
            s += c;
        }
        warp_off[NW] = s;
    }
    __syncthreads();
    if (nz) {
        int p = warp_off[w] + __popc(m & ((1u << lane) - 1u));
        sv[p]   = v;
        sidx[p] = i0 + tid;
    }
    __syncthreads();
    const int cnt = warp_off[NW];

    const float* Wb = W + (size_t)j0;
    float4 acc = make_float4(0.f, 0.f, 0.f, 0.f);

    // ---- prologue: fill the pipeline (always commit, even empty groups) ----
    #pragma unroll
    for (int s = 0; s < DEPTH; s++) {
        if (s < cnt)
            cp_async16(&stage[s][tid], Wb + (size_t)sidx[s] * U);
        cp_commit();
    }

    // ---- steady state: one wait + one consume + one issue per row ----
    for (int k = 0; k < cnt; k++) {
        cp_wait<DEPTH - 1>();
        float4 a = stage[k & (DEPTH - 1)][tid];
        float  c = sv[k];
        int n = k + DEPTH;
        if (n < cnt)
            cp_async16(&stage[n & (DEPTH - 1)][tid], Wb + (size_t)sidx[n] * U);
        cp_commit();
        acc.x = fmaf(c, a.x, acc.x);
        acc.y = fmaf(c, a.y, acc.y);
        acc.z = fmaf(c, a.z, acc.z);
        acc.w = fmaf(c, a.w, acc.w);
    }
    cp_wait<0>();

    float* yp = y + b * U + j0;
    atomicAdd(yp + 0, acc.x);
    atomicAdd(yp + 1, acc.y);
    atomicAdd(yp + 2, acc.z);
    atomicAdd(yp + 3, acc.w);

    if (!layer2) {
        // publish: this (b, jb) split-K block is done
        __threadfence();
        __syncthreads();
        if (tid == 0) atomicAdd(&g_cnt1[b * JBLK + jb], 1u);
    } else {
        // last split-K block per (b, jb) applies final ReLU in place on out
        __threadfence();
        __syncthreads();
        if (tid == 0) {
            unsigned old = atomicAdd(&g_cnt2[b * JBLK + jb], 1u);
            s_last = (old == KBLK - 1) ? 1 : 0;
        }
        __syncthreads();
        if (s_last) {
            float r0 = __ldcg(yp + 0);
            float r1 = __ldcg(yp + 1);
            float r2 = __ldcg(yp + 2);
            float r3 = __ldcg(yp + 3);
            yp[0] = fmaxf(r0, 0.0f);
            yp[1] = fmaxf(r1, 0.0f);
            yp[2] = fmaxf(r2, 0.0f);
            yp[3] = fmaxf(r3, 0.0f);
        }
    }
}

extern "C" void kernel_launch(void* const* d_in, const int* in_sizes, int n_in,
                              void* d_out, int out_size)
{
    const float* adj0 = (const float*)d_in[0];
    const float* adj1 = (const float*)d_in[1];
    const float* adj2 = (const float*)d_in[2];
    const float* nv   = (const float*)d_in[3];
    const float* w0_1 = (const float*)d_in[4];
    const float* w0_2 = (const float*)d_in[5];
    const float* w1_1 = (const float*)d_in[6];
    const float* w1_2 = (const float*)d_in[7];
    const float* w2_1 = (const float*)d_in[8];
    const float* w2_2 = (const float*)d_in[9];
    float* out = (float*)d_out;

    dist_kernel<<<512, 256>>>(adj0, adj1, adj2, nv, out);
    fused_mlp_kernel<<<NBLK, GEMV_TPB>>>(w0_1, w1_1, w2_1,
                                         w0_2, w1_2, w2_2, out);
}